// round 10
// baseline (speedup 1.0000x reference)
#include <cuda_runtime.h>
#include <cstdint>
#include <cstddef>

// ---------------------------------------------------------------------------
// HGNN_conv via tf32 mma.sync:
//   yT  = (x @ W)^T            [128f, 16384n]   (rna-rounded on store)
//   eyT = raw MT @ y, as [f][e], split-K atomics
//   eys = rna(D_v ⊙ ey)
//   out = 0.5 * D_e ⊙ (MT^T @ eys)
// R10: same R4/R8 pipeline schedule + LDSM fragments, but 4 warps/CTA in a
// 2x2 grid with 64x64 warp tiles: operand fragment duplication drops from
// (4x A, 2x B) to (2x, 2x) -> smem fragment traffic per HMMA falls 1.5x,
// which is the binding resource (L1 60% > tensor 40% in R8).
// ---------------------------------------------------------------------------

#define NN   16384
#define NE   8192
#define CIN  256
#define FOUT 128

__device__ float g_yT [FOUT * NN];   // 8 MB
__device__ float g_eyT[FOUT * NE];   // 4 MB
__device__ float g_wt [FOUT * CIN];  // 128 KB

#define BM 128
#define BN 128
#define BK 32
#define NTHR 128
#define SA0 36            // As stride (floats), CONF0 layout [m][k]; 144B
#define SA1 136           // As stride (floats), CONF1 layout [k][m]
#define SB  36            // Bs stride (floats), [n][k]; 144B
#define STAGE_FLOATS 9216 // 36864 B / 4
#define B_OFF_F 4608      // 18432 B / 4
#define SMEM_BYTES 73728  // 2 stages

// ---------------- helpers ----------------
static __device__ __forceinline__ uint32_t smem_u32(const void* p) {
    uint32_t a;
    asm("{ .reg .u64 t; cvta.to.shared.u64 t, %1; cvt.u32.u64 %0, t; }" : "=r"(a) : "l"(p));
    return a;
}
static __device__ __forceinline__ uint32_t rna(float x) {
    uint32_t o; asm("cvt.rna.tf32.f32 %0, %1;" : "=r"(o) : "f"(x)); return o;
}
static __device__ __forceinline__ float rnaf(float x) { return __uint_as_float(rna(x)); }
static __device__ __forceinline__ void cp16(uint32_t s, const void* g) {
    asm volatile("cp.async.cg.shared.global [%0], [%1], 16;" :: "r"(s), "l"(g) : "memory");
}
static __device__ __forceinline__ void cp_commit() {
    asm volatile("cp.async.commit_group;" ::: "memory");
}
static __device__ __forceinline__ void cp_wait0() {
    asm volatile("cp.async.wait_group 0;" ::: "memory");
}
static __device__ __forceinline__ void sts4(uint32_t a, uint32_t x, uint32_t y,
                                            uint32_t z, uint32_t w) {
    asm volatile("st.shared.v4.b32 [%0], {%1, %2, %3, %4};"
                 :: "r"(a), "r"(x), "r"(y), "r"(z), "r"(w) : "memory");
}
static __device__ __forceinline__ void ldsm4(uint32_t& r0, uint32_t& r1,
                                             uint32_t& r2, uint32_t& r3, uint32_t a) {
    asm volatile("ldmatrix.sync.aligned.m8n8.x4.shared.b16 {%0,%1,%2,%3}, [%4];"
                 : "=r"(r0), "=r"(r1), "=r"(r2), "=r"(r3) : "r"(a));
}
static __device__ __forceinline__ void mma8(float& c0, float& c1, float& c2, float& c3,
                                            uint32_t a0, uint32_t a1, uint32_t a2, uint32_t a3,
                                            uint32_t b0, uint32_t b1) {
    asm volatile("mma.sync.aligned.m16n8k8.row.col.f32.tf32.tf32.f32 "
                 "{%0,%1,%2,%3}, {%4,%5,%6,%7}, {%8,%9}, {%0,%1,%2,%3};"
                 : "+f"(c0), "+f"(c1), "+f"(c2), "+f"(c3)
                 : "r"(a0), "r"(a1), "r"(a2), "r"(a3), "r"(b0), "r"(b1));
}

// ---------------- small kernels ----------------
__global__ void zero2_kernel(float* __restrict__ a, size_t na4,
                             float* __restrict__ b, size_t nb4) {
    size_t i = (size_t)blockIdx.x * blockDim.x + threadIdx.x;
    size_t st = (size_t)gridDim.x * blockDim.x;
    float4 z = make_float4(0.f, 0.f, 0.f, 0.f);
    for (size_t j = i; j < na4; j += st) reinterpret_cast<float4*>(a)[j] = z;
    for (size_t j = i; j < nb4; j += st) reinterpret_cast<float4*>(b)[j] = z;
}
__global__ void prep_wt_kernel(const float* __restrict__ W, float* __restrict__ wt) {
    int idx = blockIdx.x * blockDim.x + threadIdx.x;
    if (idx < FOUT * CIN) {
        int f = idx % FOUT, c = idx / FOUT;
        wt[f * CIN + c] = rnaf(W[c * FOUT + f]);
    }
}
__global__ void scale_ey_kernel(float* __restrict__ eyT, const float* __restrict__ dv) {
    int i4 = blockIdx.x * blockDim.x + threadIdx.x;
    if (i4 < (FOUT * NE) / 4) {
        int e4 = (i4 * 4) & (NE - 1);
        float4 v = reinterpret_cast<float4*>(eyT)[i4];
        const float4 s = *reinterpret_cast<const float4*>(&dv[e4]);
        v.x = rnaf(v.x * s.x); v.y = rnaf(v.y * s.y);
        v.z = rnaf(v.z * s.z); v.w = rnaf(v.w * s.w);
        reinterpret_cast<float4*>(eyT)[i4] = v;
    }
}

// ---------------- main GEMM ----------------
// 128 threads, 4 warps in 2x2, warp tile 64x64.
// CONF 0: A resident (cp.async, pre-rounded) [m][k]; B streamed (LDG+rna+STS) [n][k]
// CONF 1: A streamed (LDG+rna+STS), source rows are k, stored [k][m]; B resident [n][k]
// EPI  0: direct store with rna   1: atomicAdd   2: atomicAdd * 0.5*rowscale[m]
template <int CONF, int EPI>
__global__ __launch_bounds__(NTHR, 2)
void mmak(const float* __restrict__ Ag, int lda,
          const float* __restrict__ Bg, int ldb,
          float* __restrict__ Cg, int ldc,
          const float* __restrict__ rowscale,
          int k_chunk)
{
    extern __shared__ float sm[];
    const int t    = threadIdx.x;
    const int lane = t & 31, wid = t >> 5;
    const int g = lane >> 2, tg = lane & 3;
    const int wm = (wid & 1) * 64, wn = (wid >> 1) * 64;
    const int m0 = blockIdx.x * BM, n0 = blockIdx.y * BN;
    const int kbase = blockIdx.z * k_chunk;
    const int KT = k_chunk / BK;

    float acc[4][8][4];
    #pragma unroll
    for (int a = 0; a < 4; ++a)
        #pragma unroll
        for (int b = 0; b < 8; ++b)
            #pragma unroll
            for (int c = 0; c < 4; ++c) acc[a][b][c] = 0.f;

    float4 rg[8];

    // ldmatrix per-lane offsets (floats) within a stage (same mapping as R8)
    const uint32_t aOffF = (uint32_t)((wm + (lane & 15)) * SA0 + (lane >> 4) * 4);
    const uint32_t bOffF = (uint32_t)((wn + (lane & 7) + (lane >> 4) * 8) * SB
                                      + ((lane >> 3) & 1) * 4);

    // ---- streamed LDG into regs for tile kt ----
    auto ldg_stream = [&](int kt) {
        const int kk = kbase + kt * BK;
        if (CONF == 0) {
            const float4* src = reinterpret_cast<const float4*>(
                Bg + (size_t)(n0 + t) * ldb + kk);
            #pragma unroll
            for (int j = 0; j < 8; ++j) rg[j] = src[j];
        } else {
            const int kr = t & 31, ml = (t >> 5) * 32;
            const float4* src = reinterpret_cast<const float4*>(
                Ag + (size_t)(kk + kr) * lda + m0 + ml);
            #pragma unroll
            for (int j = 0; j < 8; ++j) rg[j] = src[j];
        }
    };
    // ---- STS streamed regs (with rna) into stage s ----
    auto sts_stream = [&](int s) {
        float* base = sm + s * STAGE_FLOATS;
        uint32_t a;
        if (CONF == 0) {
            a = smem_u32(base + B_OFF_F + t * SB);
        } else {
            const int kr = t & 31, ml = (t >> 5) * 32;
            a = smem_u32(base + kr * SA1 + ml);
        }
        #pragma unroll
        for (int j = 0; j < 8; ++j)
            sts4(a + j * 16, rna(rg[j].x), rna(rg[j].y), rna(rg[j].z), rna(rg[j].w));
    };
    // ---- resident operand via cp.async into stage s ----
    auto cp_res = [&](int s, int kt) {
        const int kk = kbase + kt * BK;
        float* base = sm + s * STAGE_FLOATS;
        if (CONF == 0) {
            const float* src = Ag + (size_t)(m0 + t) * lda + kk;
            uint32_t a = smem_u32(base + t * SA0);
            #pragma unroll
            for (int j = 0; j < 8; ++j) cp16(a + j * 16, src + j * 4);
        } else {
            const float* src = Bg + (size_t)(n0 + t) * ldb + kk;
            uint32_t a = smem_u32(base + B_OFF_F + t * SB);
            #pragma unroll
            for (int j = 0; j < 8; ++j) cp16(a + j * 16, src + j * 4);
        }
    };
    // ---- compute one stage (LDSM fragment loads, 64x64 warp tile) ----
    auto compute = [&](int s) {
        const float* As = sm + s * STAGE_FLOATS;
        const float* Bs = As + B_OFF_F;
        const uint32_t aBase = smem_u32(As) + (aOffF << 2);
        const uint32_t bBase = smem_u32(Bs) + (bOffF << 2);
        #pragma unroll
        for (int ks = 0; ks < 4; ++ks) {
            const int k8 = ks * 8;
            uint32_t af[4][4], bf[8][2];
            if (CONF == 0) {
                #pragma unroll
                for (int mi = 0; mi < 4; ++mi)
                    ldsm4(af[mi][0], af[mi][1], af[mi][2], af[mi][3],
                          aBase + ks * 32 + mi * (16 * SA0 * 4));
            } else {
                #pragma unroll
                for (int mi = 0; mi < 4; ++mi) {
                    const int r0 = wm + mi * 16 + g, r1 = r0 + 8;
                    const int c0 = k8 + tg, c1 = c0 + 4;
                    af[mi][0] = __float_as_uint(As[c0 * SA1 + r0]);
                    af[mi][1] = __float_as_uint(As[c0 * SA1 + r1]);
                    af[mi][2] = __float_as_uint(As[c1 * SA1 + r0]);
                    af[mi][3] = __float_as_uint(As[c1 * SA1 + r1]);
                }
            }
            #pragma unroll
            for (int p = 0; p < 4; ++p)
                ldsm4(bf[2 * p][0], bf[2 * p][1], bf[2 * p + 1][0], bf[2 * p + 1][1],
                      bBase + ks * 32 + p * (16 * SB * 4));
            #pragma unroll
            for (int mi = 0; mi < 4; ++mi)
                #pragma unroll
                for (int ni = 0; ni < 8; ++ni)
                    mma8(acc[mi][ni][0], acc[mi][ni][1], acc[mi][ni][2], acc[mi][ni][3],
                         af[mi][0], af[mi][1], af[mi][2], af[mi][3],
                         bf[ni][0], bf[ni][1]);
        }
    };

    // ---- pipelined main loop (R4/R8 schedule, unchanged) ----
    ldg_stream(0);
    sts_stream(0);
    cp_res(0, 0);
    cp_commit();
    for (int kt = 0; kt < KT; ++kt) {
        const int cur = kt & 1, nxt = cur ^ 1;
        if (kt + 1 < KT) ldg_stream(kt + 1);
        cp_wait0();
        __syncthreads();
        if (kt + 1 < KT) {
            sts_stream(nxt);
            cp_res(nxt, kt + 1);
            cp_commit();
        }
        compute(cur);
        __syncthreads();
    }

    // ---- epilogue ----
    #pragma unroll
    for (int mi = 0; mi < 4; ++mi) {
        const int r0 = m0 + wm + mi * 16 + g;
        const int r1 = r0 + 8;
        #pragma unroll
        for (int ni = 0; ni < 8; ++ni) {
            const int c0 = n0 + wn + ni * 8 + tg * 2;
            float* p0 = Cg + (size_t)r0 * ldc + c0;
            float* p1 = Cg + (size_t)r1 * ldc + c0;
            if (EPI == 0) {
                p0[0] = rnaf(acc[mi][ni][0]); p0[1] = rnaf(acc[mi][ni][1]);
                p1[0] = rnaf(acc[mi][ni][2]); p1[1] = rnaf(acc[mi][ni][3]);
            } else if (EPI == 1) {
                atomicAdd(&p0[0], acc[mi][ni][0]); atomicAdd(&p0[1], acc[mi][ni][1]);
                atomicAdd(&p1[0], acc[mi][ni][2]); atomicAdd(&p1[1], acc[mi][ni][3]);
            } else {
                const float s0 = 0.5f * rowscale[r0];
                const float s1 = 0.5f * rowscale[r1];
                atomicAdd(&p0[0], s0 * acc[mi][ni][0]); atomicAdd(&p0[1], s0 * acc[mi][ni][1]);
                atomicAdd(&p1[0], s1 * acc[mi][ni][2]); atomicAdd(&p1[1], s1 * acc[mi][ni][3]);
            }
        }
    }
}

// ---------------- launch ----------------
extern "C" void kernel_launch(void* const* d_in, const int* in_sizes, int n_in,
                              void* d_out, int out_size) {
    const float *x = nullptr, *w = nullptr, *mt = nullptr, *dv = nullptr, *de = nullptr;
    for (int i = 0; i < n_in; ++i) {
        switch (in_sizes[i]) {
            case NN * CIN:   x  = (const float*)d_in[i]; break;
            case CIN * FOUT: w  = (const float*)d_in[i]; break;
            case 134217728:  mt = (const float*)d_in[i]; break;
            case NE:         dv = (const float*)d_in[i]; break;
            case NN:         de = (const float*)d_in[i]; break;
        }
    }
    float* out = (float*)d_out;
    float *yT, *eyT, *wt;
    { void* p; cudaGetSymbolAddress(&p, g_yT);  yT  = (float*)p; }
    { void* p; cudaGetSymbolAddress(&p, g_eyT); eyT = (float*)p; }
    { void* p; cudaGetSymbolAddress(&p, g_wt);  wt  = (float*)p; }

    cudaFuncSetAttribute(mmak<0, 0>, cudaFuncAttributeMaxDynamicSharedMemorySize, SMEM_BYTES);
    cudaFuncSetAttribute(mmak<0, 1>, cudaFuncAttributeMaxDynamicSharedMemorySize, SMEM_BYTES);
    cudaFuncSetAttribute(mmak<1, 2>, cudaFuncAttributeMaxDynamicSharedMemorySize, SMEM_BYTES);

    zero2_kernel<<<512, 256>>>(eyT, (size_t)(FOUT * NE) / 4, out, (size_t)(NN * FOUT) / 4);
    prep_wt_kernel<<<(FOUT * CIN + 255) / 256, 256>>>(w, wt);

    // G1: yT[f][n] = rna( sum_c wt[f][c] * x[n][c] )
    mmak<0, 0><<<dim3(1, NN / BN, 1), NTHR, SMEM_BYTES>>>(
        wt, CIN, x, CIN, yT, NN, nullptr, CIN);

    // G2: eyT[f][e] += sum_n yT[f][n] * MT[e][n]   (split-K = 4)
    mmak<0, 1><<<dim3(1, NE / BN, 4), NTHR, SMEM_BYTES>>>(
        yT, NN, mt, NN, eyT, NE, nullptr, NN / 4);

    scale_ey_kernel<<<(FOUT * NE / 4 + 255) / 256, 256>>>(eyT, dv);

    // G3: out[v][f] += 0.5*De[v] * sum_e MT[e][v] * eyT[f][e]   (split-K = 2)
    mmak<1, 2><<<dim3(NN / BM, 1, 2), NTHR, SMEM_BYTES>>>(
        mt, NN, eyT, NE, out, FOUT, de, NE / 2);
}

// round 11
// speedup vs baseline: 1.1265x; 1.1265x over previous
#include <cuda_runtime.h>
#include <cstdint>
#include <cstddef>

// ---------------------------------------------------------------------------
// HGNN_conv via tf32 mma.sync:
//   yT  = (x @ W)^T            [128f, 16384n]   (rna-rounded on store)
//   eyT = raw MT @ y, as [f][e], split-K atomics
//   eys = rna(D_v ⊙ ey)
//   out = 0.5 * D_e ⊙ (MT^T @ eys)
// R11: R8 (651us: LDSM fragments, 2x4 warp grid, LDG->STS streaming, 2 CTAs/SM)
// with the smem double-buffer replaced by a 3-stage ring -> the trailing
// __syncthreads() per stage is provably removable (writes at iter kt target
// stage (kt+1)%3; stage kt%3 can only be overwritten at iter kt+3, which is
// fenced by the single mid-loop barrier). Halves barrier count, deepens
// cp.async by one stage.
// ---------------------------------------------------------------------------

#define NN   16384
#define NE   8192
#define CIN  256
#define FOUT 128

__device__ float g_yT [FOUT * NN];   // 8 MB
__device__ float g_eyT[FOUT * NE];   // 4 MB
__device__ float g_wt [FOUT * CIN];  // 128 KB

#define BM 128
#define BN 128
#define BK 32
#define NTHR 256
#define SA0 36             // As stride (floats), CONF0 layout [m][k]; 144B
#define SA1 136            // As stride (floats), CONF1 layout [k][m]
#define SB  36             // Bs stride (floats), [n][k]; 144B
#define STAGE_FLOATS 9216  // 36864 B / 4
#define B_OFF_F 4608       // 18432 B / 4
#define NSTAGE 3
#define SMEM_BYTES 110592  // 3 stages; 2 CTAs/SM = 221184 B fits 228KB

// ---------------- helpers ----------------
static __device__ __forceinline__ uint32_t smem_u32(const void* p) {
    uint32_t a;
    asm("{ .reg .u64 t; cvta.to.shared.u64 t, %1; cvt.u32.u64 %0, t; }" : "=r"(a) : "l"(p));
    return a;
}
static __device__ __forceinline__ uint32_t rna(float x) {
    uint32_t o; asm("cvt.rna.tf32.f32 %0, %1;" : "=r"(o) : "f"(x)); return o;
}
static __device__ __forceinline__ float rnaf(float x) { return __uint_as_float(rna(x)); }
static __device__ __forceinline__ void cp16(uint32_t s, const void* g) {
    asm volatile("cp.async.cg.shared.global [%0], [%1], 16;" :: "r"(s), "l"(g) : "memory");
}
static __device__ __forceinline__ void cp_commit() {
    asm volatile("cp.async.commit_group;" ::: "memory");
}
template <int N>
static __device__ __forceinline__ void cp_wait() {
    asm volatile("cp.async.wait_group %0;" :: "n"(N) : "memory");
}
static __device__ __forceinline__ void sts4(uint32_t a, uint32_t x, uint32_t y,
                                            uint32_t z, uint32_t w) {
    asm volatile("st.shared.v4.b32 [%0], {%1, %2, %3, %4};"
                 :: "r"(a), "r"(x), "r"(y), "r"(z), "r"(w) : "memory");
}
static __device__ __forceinline__ void ldsm4(uint32_t& r0, uint32_t& r1,
                                             uint32_t& r2, uint32_t& r3, uint32_t a) {
    asm volatile("ldmatrix.sync.aligned.m8n8.x4.shared.b16 {%0,%1,%2,%3}, [%4];"
                 : "=r"(r0), "=r"(r1), "=r"(r2), "=r"(r3) : "r"(a));
}
static __device__ __forceinline__ void mma8(float& c0, float& c1, float& c2, float& c3,
                                            uint32_t a0, uint32_t a1, uint32_t a2, uint32_t a3,
                                            uint32_t b0, uint32_t b1) {
    asm volatile("mma.sync.aligned.m16n8k8.row.col.f32.tf32.tf32.f32 "
                 "{%0,%1,%2,%3}, {%4,%5,%6,%7}, {%8,%9}, {%0,%1,%2,%3};"
                 : "+f"(c0), "+f"(c1), "+f"(c2), "+f"(c3)
                 : "r"(a0), "r"(a1), "r"(a2), "r"(a3), "r"(b0), "r"(b1));
}

// ---------------- small kernels ----------------
__global__ void zero2_kernel(float* __restrict__ a, size_t na4,
                             float* __restrict__ b, size_t nb4) {
    size_t i = (size_t)blockIdx.x * blockDim.x + threadIdx.x;
    size_t st = (size_t)gridDim.x * blockDim.x;
    float4 z = make_float4(0.f, 0.f, 0.f, 0.f);
    for (size_t j = i; j < na4; j += st) reinterpret_cast<float4*>(a)[j] = z;
    for (size_t j = i; j < nb4; j += st) reinterpret_cast<float4*>(b)[j] = z;
}
__global__ void prep_wt_kernel(const float* __restrict__ W, float* __restrict__ wt) {
    int idx = blockIdx.x * blockDim.x + threadIdx.x;
    if (idx < FOUT * CIN) {
        int f = idx % FOUT, c = idx / FOUT;
        wt[f * CIN + c] = rnaf(W[c * FOUT + f]);
    }
}
__global__ void scale_ey_kernel(float* __restrict__ eyT, const float* __restrict__ dv) {
    int i4 = blockIdx.x * blockDim.x + threadIdx.x;
    if (i4 < (FOUT * NE) / 4) {
        int e4 = (i4 * 4) & (NE - 1);
        float4 v = reinterpret_cast<float4*>(eyT)[i4];
        const float4 s = *reinterpret_cast<const float4*>(&dv[e4]);
        v.x = rnaf(v.x * s.x); v.y = rnaf(v.y * s.y);
        v.z = rnaf(v.z * s.z); v.w = rnaf(v.w * s.w);
        reinterpret_cast<float4*>(eyT)[i4] = v;
    }
}

// ---------------- main GEMM ----------------
// 256 threads, 8 warps in 2x4, warp tile 64x32 (R8 geometry).
// CONF 0: A resident (cp.async, pre-rounded) [m][k]; B streamed (LDG+rna+STS) [n][k]
// CONF 1: A streamed (LDG+rna+STS), source rows are k, stored [k][m]; B resident [n][k]
// EPI  0: direct store with rna   1: atomicAdd   2: atomicAdd * 0.5*rowscale[m]
template <int CONF, int EPI>
__global__ __launch_bounds__(NTHR)
void mmak(const float* __restrict__ Ag, int lda,
          const float* __restrict__ Bg, int ldb,
          float* __restrict__ Cg, int ldc,
          const float* __restrict__ rowscale,
          int k_chunk)
{
    extern __shared__ float sm[];
    const int t    = threadIdx.x;
    const int lane = t & 31, wid = t >> 5;
    const int g = lane >> 2, tg = lane & 3;
    const int wm = (wid & 1) * 64, wn = (wid >> 1) * 32;
    const int m0 = blockIdx.x * BM, n0 = blockIdx.y * BN;
    const int kbase = blockIdx.z * k_chunk;
    const int KT = k_chunk / BK;

    float acc[4][4][4];
    #pragma unroll
    for (int a = 0; a < 4; ++a)
        #pragma unroll
        for (int b = 0; b < 4; ++b)
            #pragma unroll
            for (int c = 0; c < 4; ++c) acc[a][b][c] = 0.f;

    float4 rg[4];

    // ldmatrix per-lane offsets (floats) within a stage (R8 mapping)
    const uint32_t aOffF = (uint32_t)((wm + (lane & 15)) * SA0 + (lane >> 4) * 4);
    const uint32_t bOffF = (uint32_t)((wn + (lane & 7) + (lane >> 4) * 8) * SB
                                      + ((lane >> 3) & 1) * 4);

    // ---- streamed LDG into regs for tile kt ----
    auto ldg_stream = [&](int kt) {
        const int kk = kbase + kt * BK;
        if (CONF == 0) {
            const int n = t >> 1, h = t & 1;
            const float4* src = reinterpret_cast<const float4*>(
                Bg + (size_t)(n0 + n) * ldb + kk + h * 16);
            #pragma unroll
            for (int j = 0; j < 4; ++j) rg[j] = src[j];
        } else {
            const int kr = t >> 3, ml = (t & 7) * 16;
            const float4* src = reinterpret_cast<const float4*>(
                Ag + (size_t)(kk + kr) * lda + m0 + ml);
            #pragma unroll
            for (int j = 0; j < 4; ++j) rg[j] = src[j];
        }
    };
    // ---- STS streamed regs (with rna) into stage s ----
    auto sts_stream = [&](int s) {
        float* base = sm + s * STAGE_FLOATS;
        uint32_t a;
        if (CONF == 0) {
            const int n = t >> 1, h = t & 1;
            a = smem_u32(base + B_OFF_F + n * SB + h * 16);
        } else {
            const int kr = t >> 3, ml = (t & 7) * 16;
            a = smem_u32(base + kr * SA1 + ml);
        }
        #pragma unroll
        for (int j = 0; j < 4; ++j)
            sts4(a + j * 16, rna(rg[j].x), rna(rg[j].y), rna(rg[j].z), rna(rg[j].w));
    };
    // ---- resident operand via cp.async into stage s ----
    auto cp_res = [&](int s, int kt) {
        const int kk = kbase + kt * BK;
        float* base = sm + s * STAGE_FLOATS;
        const int r = t >> 1, h = t & 1;
        if (CONF == 0) {
            const float* src = Ag + (size_t)(m0 + r) * lda + kk + h * 16;
            uint32_t a = smem_u32(base + r * SA0 + h * 16);
            #pragma unroll
            for (int j = 0; j < 4; ++j) cp16(a + j * 16, src + j * 4);
        } else {
            const float* src = Bg + (size_t)(n0 + r) * ldb + kk + h * 16;
            uint32_t a = smem_u32(base + B_OFF_F + r * SB + h * 16);
            #pragma unroll
            for (int j = 0; j < 4; ++j) cp16(a + j * 16, src + j * 4);
        }
    };
    // ---- compute one stage (LDSM fragment loads, R8) ----
    auto compute = [&](int s) {
        const float* As = sm + s * STAGE_FLOATS;
        const float* Bs = As + B_OFF_F;
        const uint32_t aBase = smem_u32(As) + (aOffF << 2);
        const uint32_t bBase = smem_u32(Bs) + (bOffF << 2);
        #pragma unroll
        for (int ks = 0; ks < 4; ++ks) {
            const int k8 = ks * 8;
            uint32_t af[4][4], bf[4][2];
            if (CONF == 0) {
                #pragma unroll
                for (int mi = 0; mi < 4; ++mi)
                    ldsm4(af[mi][0], af[mi][1], af[mi][2], af[mi][3],
                          aBase + ks * 32 + mi * (16 * SA0 * 4));
            } else {
                #pragma unroll
                for (int mi = 0; mi < 4; ++mi) {
                    const int r0 = wm + mi * 16 + g, r1 = r0 + 8;
                    const int c0 = k8 + tg, c1 = c0 + 4;
                    af[mi][0] = __float_as_uint(As[c0 * SA1 + r0]);
                    af[mi][1] = __float_as_uint(As[c0 * SA1 + r1]);
                    af[mi][2] = __float_as_uint(As[c1 * SA1 + r0]);
                    af[mi][3] = __float_as_uint(As[c1 * SA1 + r1]);
                }
            }
            #pragma unroll
            for (int p = 0; p < 2; ++p)
                ldsm4(bf[2 * p][0], bf[2 * p][1], bf[2 * p + 1][0], bf[2 * p + 1][1],
                      bBase + ks * 32 + p * (16 * SB * 4));
            #pragma unroll
            for (int mi = 0; mi < 4; ++mi)
                #pragma unroll
                for (int ni = 0; ni < 4; ++ni)
                    mma8(acc[mi][ni][0], acc[mi][ni][1], acc[mi][ni][2], acc[mi][ni][3],
                         af[mi][0], af[mi][1], af[mi][2], af[mi][3],
                         bf[ni][0], bf[ni][1]);
        }
    };

    // ---- prologue: fill stage 0 ----
    ldg_stream(0);
    sts_stream(0);
    cp_res(0, 0);
    cp_commit();

    // ---- main loop: 3-stage ring, ONE barrier per stage ----
    // iter kt: reads stage kt%3, writes stage (kt+1)%3. Stage kt%3 cannot be
    // overwritten until iter kt+3, which is fenced by the barriers at kt+1,kt+2.
    for (int kt = 0; kt < KT; ++kt) {
        const int cur = kt % NSTAGE, nxt = (kt + 1) % NSTAGE;
        const bool more = (kt + 1 < KT);
        if (more) {
            ldg_stream(kt + 1);
            sts_stream(nxt);
            cp_res(nxt, kt + 1);
            cp_commit();
            cp_wait<1>();        // stage cur's group (committed at kt-1) done
        } else {
            cp_wait<0>();
        }
        __syncthreads();         // stage cur fully visible to all warps
        compute(cur);
    }

    // ---- epilogue ----
    #pragma unroll
    for (int mi = 0; mi < 4; ++mi) {
        const int r0 = m0 + wm + mi * 16 + g;
        const int r1 = r0 + 8;
        #pragma unroll
        for (int ni = 0; ni < 4; ++ni) {
            const int c0 = n0 + wn + ni * 8 + tg * 2;
            float* p0 = Cg + (size_t)r0 * ldc + c0;
            float* p1 = Cg + (size_t)r1 * ldc + c0;
            if (EPI == 0) {
                p0[0] = rnaf(acc[mi][ni][0]); p0[1] = rnaf(acc[mi][ni][1]);
                p1[0] = rnaf(acc[mi][ni][2]); p1[1] = rnaf(acc[mi][ni][3]);
            } else if (EPI == 1) {
                atomicAdd(&p0[0], acc[mi][ni][0]); atomicAdd(&p0[1], acc[mi][ni][1]);
                atomicAdd(&p1[0], acc[mi][ni][2]); atomicAdd(&p1[1], acc[mi][ni][3]);
            } else {
                const float s0 = 0.5f * rowscale[r0];
                const float s1 = 0.5f * rowscale[r1];
                atomicAdd(&p0[0], s0 * acc[mi][ni][0]); atomicAdd(&p0[1], s0 * acc[mi][ni][1]);
                atomicAdd(&p1[0], s1 * acc[mi][ni][2]); atomicAdd(&p1[1], s1 * acc[mi][ni][3]);
            }
        }
    }
}

// ---------------- launch ----------------
extern "C" void kernel_launch(void* const* d_in, const int* in_sizes, int n_in,
                              void* d_out, int out_size) {
    const float *x = nullptr, *w = nullptr, *mt = nullptr, *dv = nullptr, *de = nullptr;
    for (int i = 0; i < n_in; ++i) {
        switch (in_sizes[i]) {
            case NN * CIN:   x  = (const float*)d_in[i]; break;
            case CIN * FOUT: w  = (const float*)d_in[i]; break;
            case 134217728:  mt = (const float*)d_in[i]; break;
            case NE:         dv = (const float*)d_in[i]; break;
            case NN:         de = (const float*)d_in[i]; break;
        }
    }
    float* out = (float*)d_out;
    float *yT, *eyT, *wt;
    { void* p; cudaGetSymbolAddress(&p, g_yT);  yT  = (float*)p; }
    { void* p; cudaGetSymbolAddress(&p, g_eyT); eyT = (float*)p; }
    { void* p; cudaGetSymbolAddress(&p, g_wt);  wt  = (float*)p; }

    cudaFuncSetAttribute(mmak<0, 0>, cudaFuncAttributeMaxDynamicSharedMemorySize, SMEM_BYTES);
    cudaFuncSetAttribute(mmak<0, 1>, cudaFuncAttributeMaxDynamicSharedMemorySize, SMEM_BYTES);
    cudaFuncSetAttribute(mmak<1, 2>, cudaFuncAttributeMaxDynamicSharedMemorySize, SMEM_BYTES);

    zero2_kernel<<<512, 256>>>(eyT, (size_t)(FOUT * NE) / 4, out, (size_t)(NN * FOUT) / 4);
    prep_wt_kernel<<<(FOUT * CIN + 255) / 256, 256>>>(w, wt);

    // G1: yT[f][n] = rna( sum_c wt[f][c] * x[n][c] )
    mmak<0, 0><<<dim3(1, NN / BN, 1), NTHR, SMEM_BYTES>>>(
        wt, CIN, x, CIN, yT, NN, nullptr, CIN);

    // G2: eyT[f][e] += sum_n yT[f][n] * MT[e][n]   (split-K = 4)
    mmak<0, 1><<<dim3(1, NE / BN, 4), NTHR, SMEM_BYTES>>>(
        yT, NN, mt, NN, eyT, NE, nullptr, NN / 4);

    scale_ey_kernel<<<(FOUT * NE / 4 + 255) / 256, 256>>>(eyT, dv);

    // G3: out[v][f] += 0.5*De[v] * sum_e MT[e][v] * eyT[f][e]   (split-K = 2)
    mmak<1, 2><<<dim3(NN / BM, 1, 2), NTHR, SMEM_BYTES>>>(
        mt, NN, eyT, NE, out, FOUT, de, NE / 2);
}

// round 12
// speedup vs baseline: 1.1822x; 1.0494x over previous
#include <cuda_runtime.h>
#include <cstdint>
#include <cstddef>

// ---------------------------------------------------------------------------
// HGNN_conv via tf32 mma.sync:
//   yT  = (x @ W)^T            [128f, 16384n]   (rna-rounded on store)
//   eyT = raw MT @ y, as [f][e], split-K atomics
//   eys = rna(D_v ⊙ ey)
//   out = 0.5 * D_e ⊙ (MT^T @ eys)
// R12: R8 (651us) byte-for-byte inner loop, with the smem double-buffer
// replaced by a 3-stage ring so ONLY the trailing __syncthreads() is removed.
// Safety: iter kt writes stage (kt+1)%3 post-barrier; stage kt%3 is next
// written at iter kt+2, behind two barrier instances -> no reader overlap.
// ---------------------------------------------------------------------------

#define NN   16384
#define NE   8192
#define CIN  256
#define FOUT 128

__device__ float g_yT [FOUT * NN];   // 8 MB
__device__ float g_eyT[FOUT * NE];   // 4 MB
__device__ float g_wt [FOUT * CIN];  // 128 KB

#define BM 128
#define BN 128
#define BK 32
#define NTHR 256
#define SA0 36             // As stride (floats), CONF0 layout [m][k]; 144B
#define SA1 136            // As stride (floats), CONF1 layout [k][m]
#define SB  36             // Bs stride (floats), [n][k]; 144B
#define STAGE_FLOATS 9216  // 36864 B / 4
#define B_OFF_F 4608       // 18432 B / 4
#define NSTAGE 3
#define SMEM_BYTES 110592  // 3 stages; 2 CTAs/SM = 221184 B <= 228KB

// ---------------- helpers ----------------
static __device__ __forceinline__ uint32_t smem_u32(const void* p) {
    uint32_t a;
    asm("{ .reg .u64 t; cvta.to.shared.u64 t, %1; cvt.u32.u64 %0, t; }" : "=r"(a) : "l"(p));
    return a;
}
static __device__ __forceinline__ uint32_t rna(float x) {
    uint32_t o; asm("cvt.rna.tf32.f32 %0, %1;" : "=r"(o) : "f"(x)); return o;
}
static __device__ __forceinline__ float rnaf(float x) { return __uint_as_float(rna(x)); }
static __device__ __forceinline__ void cp16(uint32_t s, const void* g) {
    asm volatile("cp.async.cg.shared.global [%0], [%1], 16;" :: "r"(s), "l"(g) : "memory");
}
static __device__ __forceinline__ void cp_commit() {
    asm volatile("cp.async.commit_group;" ::: "memory");
}
static __device__ __forceinline__ void cp_wait0() {
    asm volatile("cp.async.wait_group 0;" ::: "memory");
}
static __device__ __forceinline__ void sts4(uint32_t a, uint32_t x, uint32_t y,
                                            uint32_t z, uint32_t w) {
    asm volatile("st.shared.v4.b32 [%0], {%1, %2, %3, %4};"
                 :: "r"(a), "r"(x), "r"(y), "r"(z), "r"(w) : "memory");
}
static __device__ __forceinline__ void ldsm4(uint32_t& r0, uint32_t& r1,
                                             uint32_t& r2, uint32_t& r3, uint32_t a) {
    asm volatile("ldmatrix.sync.aligned.m8n8.x4.shared.b16 {%0,%1,%2,%3}, [%4];"
                 : "=r"(r0), "=r"(r1), "=r"(r2), "=r"(r3) : "r"(a));
}
static __device__ __forceinline__ void mma8(float& c0, float& c1, float& c2, float& c3,
                                            uint32_t a0, uint32_t a1, uint32_t a2, uint32_t a3,
                                            uint32_t b0, uint32_t b1) {
    asm volatile("mma.sync.aligned.m16n8k8.row.col.f32.tf32.tf32.f32 "
                 "{%0,%1,%2,%3}, {%4,%5,%6,%7}, {%8,%9}, {%0,%1,%2,%3};"
                 : "+f"(c0), "+f"(c1), "+f"(c2), "+f"(c3)
                 : "r"(a0), "r"(a1), "r"(a2), "r"(a3), "r"(b0), "r"(b1));
}

// ---------------- small kernels ----------------
__global__ void zero2_kernel(float* __restrict__ a, size_t na4,
                             float* __restrict__ b, size_t nb4) {
    size_t i = (size_t)blockIdx.x * blockDim.x + threadIdx.x;
    size_t st = (size_t)gridDim.x * blockDim.x;
    float4 z = make_float4(0.f, 0.f, 0.f, 0.f);
    for (size_t j = i; j < na4; j += st) reinterpret_cast<float4*>(a)[j] = z;
    for (size_t j = i; j < nb4; j += st) reinterpret_cast<float4*>(b)[j] = z;
}
__global__ void prep_wt_kernel(const float* __restrict__ W, float* __restrict__ wt) {
    int idx = blockIdx.x * blockDim.x + threadIdx.x;
    if (idx < FOUT * CIN) {
        int f = idx % FOUT, c = idx / FOUT;
        wt[f * CIN + c] = rnaf(W[c * FOUT + f]);
    }
}
__global__ void scale_ey_kernel(float* __restrict__ eyT, const float* __restrict__ dv) {
    int i4 = blockIdx.x * blockDim.x + threadIdx.x;
    if (i4 < (FOUT * NE) / 4) {
        int e4 = (i4 * 4) & (NE - 1);
        float4 v = reinterpret_cast<float4*>(eyT)[i4];
        const float4 s = *reinterpret_cast<const float4*>(&dv[e4]);
        v.x = rnaf(v.x * s.x); v.y = rnaf(v.y * s.y);
        v.z = rnaf(v.z * s.z); v.w = rnaf(v.w * s.w);
        reinterpret_cast<float4*>(eyT)[i4] = v;
    }
}

// ---------------- main GEMM ----------------
// 256 threads, 8 warps in 2x4, warp tile 64x32 (R8 geometry).
// CONF 0: A resident (cp.async, pre-rounded) [m][k]; B streamed (LDG+rna+STS) [n][k]
// CONF 1: A streamed (LDG+rna+STS), source rows are k, stored [k][m]; B resident [n][k]
// EPI  0: direct store with rna   1: atomicAdd   2: atomicAdd * 0.5*rowscale[m]
template <int CONF, int EPI>
__global__ __launch_bounds__(NTHR)
void mmak(const float* __restrict__ Ag, int lda,
          const float* __restrict__ Bg, int ldb,
          float* __restrict__ Cg, int ldc,
          const float* __restrict__ rowscale,
          int k_chunk)
{
    extern __shared__ float sm[];
    const int t    = threadIdx.x;
    const int lane = t & 31, wid = t >> 5;
    const int g = lane >> 2, tg = lane & 3;
    const int wm = (wid & 1) * 64, wn = (wid >> 1) * 32;
    const int m0 = blockIdx.x * BM, n0 = blockIdx.y * BN;
    const int kbase = blockIdx.z * k_chunk;
    const int KT = k_chunk / BK;

    float acc[4][4][4];
    #pragma unroll
    for (int a = 0; a < 4; ++a)
        #pragma unroll
        for (int b = 0; b < 4; ++b)
            #pragma unroll
            for (int c = 0; c < 4; ++c) acc[a][b][c] = 0.f;

    float4 rg[4];

    // ldmatrix per-lane offsets (floats) within a stage (R8 mapping)
    const uint32_t aOffF = (uint32_t)((wm + (lane & 15)) * SA0 + (lane >> 4) * 4);
    const uint32_t bOffF = (uint32_t)((wn + (lane & 7) + (lane >> 4) * 8) * SB
                                      + ((lane >> 3) & 1) * 4);

    // ---- streamed LDG into regs for tile kt ----
    auto ldg_stream = [&](int kt) {
        const int kk = kbase + kt * BK;
        if (CONF == 0) {
            const int n = t >> 1, h = t & 1;
            const float4* src = reinterpret_cast<const float4*>(
                Bg + (size_t)(n0 + n) * ldb + kk + h * 16);
            #pragma unroll
            for (int j = 0; j < 4; ++j) rg[j] = src[j];
        } else {
            const int kr = t >> 3, ml = (t & 7) * 16;
            const float4* src = reinterpret_cast<const float4*>(
                Ag + (size_t)(kk + kr) * lda + m0 + ml);
            #pragma unroll
            for (int j = 0; j < 4; ++j) rg[j] = src[j];
        }
    };
    // ---- STS streamed regs (with rna) into stage s ----
    auto sts_stream = [&](int s) {
        float* base = sm + s * STAGE_FLOATS;
        uint32_t a;
        if (CONF == 0) {
            const int n = t >> 1, h = t & 1;
            a = smem_u32(base + B_OFF_F + n * SB + h * 16);
        } else {
            const int kr = t >> 3, ml = (t & 7) * 16;
            a = smem_u32(base + kr * SA1 + ml);
        }
        #pragma unroll
        for (int j = 0; j < 4; ++j)
            sts4(a + j * 16, rna(rg[j].x), rna(rg[j].y), rna(rg[j].z), rna(rg[j].w));
    };
    // ---- resident operand via cp.async into stage s ----
    auto cp_res = [&](int s, int kt) {
        const int kk = kbase + kt * BK;
        float* base = sm + s * STAGE_FLOATS;
        const int r = t >> 1, h = t & 1;
        if (CONF == 0) {
            const float* src = Ag + (size_t)(m0 + r) * lda + kk + h * 16;
            uint32_t a = smem_u32(base + r * SA0 + h * 16);
            #pragma unroll
            for (int j = 0; j < 4; ++j) cp16(a + j * 16, src + j * 4);
        } else {
            const float* src = Bg + (size_t)(n0 + r) * ldb + kk + h * 16;
            uint32_t a = smem_u32(base + B_OFF_F + r * SB + h * 16);
            #pragma unroll
            for (int j = 0; j < 4; ++j) cp16(a + j * 16, src + j * 4);
        }
    };
    // ---- compute one stage (LDSM fragment loads, R8) ----
    auto compute = [&](int s) {
        const float* As = sm + s * STAGE_FLOATS;
        const float* Bs = As + B_OFF_F;
        const uint32_t aBase = smem_u32(As) + (aOffF << 2);
        const uint32_t bBase = smem_u32(Bs) + (bOffF << 2);
        #pragma unroll
        for (int ks = 0; ks < 4; ++ks) {
            const int k8 = ks * 8;
            uint32_t af[4][4], bf[4][2];
            if (CONF == 0) {
                #pragma unroll
                for (int mi = 0; mi < 4; ++mi)
                    ldsm4(af[mi][0], af[mi][1], af[mi][2], af[mi][3],
                          aBase + ks * 32 + mi * (16 * SA0 * 4));
            } else {
                #pragma unroll
                for (int mi = 0; mi < 4; ++mi) {
                    const int r0 = wm + mi * 16 + g, r1 = r0 + 8;
                    const int c0 = k8 + tg, c1 = c0 + 4;
                    af[mi][0] = __float_as_uint(As[c0 * SA1 + r0]);
                    af[mi][1] = __float_as_uint(As[c0 * SA1 + r1]);
                    af[mi][2] = __float_as_uint(As[c1 * SA1 + r0]);
                    af[mi][3] = __float_as_uint(As[c1 * SA1 + r1]);
                }
            }
            #pragma unroll
            for (int p = 0; p < 2; ++p)
                ldsm4(bf[2 * p][0], bf[2 * p][1], bf[2 * p + 1][0], bf[2 * p + 1][1],
                      bBase + ks * 32 + p * (16 * SB * 4));
            #pragma unroll
            for (int mi = 0; mi < 4; ++mi)
                #pragma unroll
                for (int ni = 0; ni < 4; ++ni)
                    mma8(acc[mi][ni][0], acc[mi][ni][1], acc[mi][ni][2], acc[mi][ni][3],
                         af[mi][0], af[mi][1], af[mi][2], af[mi][3],
                         bf[ni][0], bf[ni][1]);
        }
    };

    // ---- prologue: fill stage 0 (R8) ----
    ldg_stream(0);
    sts_stream(0);
    cp_res(0, 0);
    cp_commit();

    // ---- main loop: R8 body, 3-stage ring, NO trailing barrier ----
    for (int kt = 0; kt < KT; ++kt) {
        const int cur = kt % NSTAGE, nxt = (kt + 1) % NSTAGE;
        const bool more = (kt + 1 < KT);
        if (more) ldg_stream(kt + 1);
        cp_wait0();
        __syncthreads();
        if (more) {
            sts_stream(nxt);
            cp_res(nxt, kt + 1);
            cp_commit();
        }
        compute(cur);
        // trailing barrier removed: stage cur next written at iter kt+2,
        // which sits behind two __syncthreads instances.
    }

    // ---- epilogue ----
    #pragma unroll
    for (int mi = 0; mi < 4; ++mi) {
        const int r0 = m0 + wm + mi * 16 + g;
        const int r1 = r0 + 8;
        #pragma unroll
        for (int ni = 0; ni < 4; ++ni) {
            const int c0 = n0 + wn + ni * 8 + tg * 2;
            float* p0 = Cg + (size_t)r0 * ldc + c0;
            float* p1 = Cg + (size_t)r1 * ldc + c0;
            if (EPI == 0) {
                p0[0] = rnaf(acc[mi][ni][0]); p0[1] = rnaf(acc[mi][ni][1]);
                p1[0] = rnaf(acc[mi][ni][2]); p1[1] = rnaf(acc[mi][ni][3]);
            } else if (EPI == 1) {
                atomicAdd(&p0[0], acc[mi][ni][0]); atomicAdd(&p0[1], acc[mi][ni][1]);
                atomicAdd(&p1[0], acc[mi][ni][2]); atomicAdd(&p1[1], acc[mi][ni][3]);
            } else {
                const float s0 = 0.5f * rowscale[r0];
                const float s1 = 0.5f * rowscale[r1];
                atomicAdd(&p0[0], s0 * acc[mi][ni][0]); atomicAdd(&p0[1], s0 * acc[mi][ni][1]);
                atomicAdd(&p1[0], s1 * acc[mi][ni][2]); atomicAdd(&p1[1], s1 * acc[mi][ni][3]);
            }
        }
    }
}

// ---------------- launch ----------------
extern "C" void kernel_launch(void* const* d_in, const int* in_sizes, int n_in,
                              void* d_out, int out_size) {
    const float *x = nullptr, *w = nullptr, *mt = nullptr, *dv = nullptr, *de = nullptr;
    for (int i = 0; i < n_in; ++i) {
        switch (in_sizes[i]) {
            case NN * CIN:   x  = (const float*)d_in[i]; break;
            case CIN * FOUT: w  = (const float*)d_in[i]; break;
            case 134217728:  mt = (const float*)d_in[i]; break;
            case NE:         dv = (const float*)d_in[i]; break;
            case NN:         de = (const float*)d_in[i]; break;
        }
    }
    float* out = (float*)d_out;
    float *yT, *eyT, *wt;
    { void* p; cudaGetSymbolAddress(&p, g_yT);  yT  = (float*)p; }
    { void* p; cudaGetSymbolAddress(&p, g_eyT); eyT = (float*)p; }
    { void* p; cudaGetSymbolAddress(&p, g_wt);  wt  = (float*)p; }

    cudaFuncSetAttribute(mmak<0, 0>, cudaFuncAttributeMaxDynamicSharedMemorySize, SMEM_BYTES);
    cudaFuncSetAttribute(mmak<0, 1>, cudaFuncAttributeMaxDynamicSharedMemorySize, SMEM_BYTES);
    cudaFuncSetAttribute(mmak<1, 2>, cudaFuncAttributeMaxDynamicSharedMemorySize, SMEM_BYTES);

    zero2_kernel<<<512, 256>>>(eyT, (size_t)(FOUT * NE) / 4, out, (size_t)(NN * FOUT) / 4);
    prep_wt_kernel<<<(FOUT * CIN + 255) / 256, 256>>>(w, wt);

    // G1: yT[f][n] = rna( sum_c wt[f][c] * x[n][c] )
    mmak<0, 0><<<dim3(1, NN / BN, 1), NTHR, SMEM_BYTES>>>(
        wt, CIN, x, CIN, yT, NN, nullptr, CIN);

    // G2: eyT[f][e] += sum_n yT[f][n] * MT[e][n]   (split-K = 4)
    mmak<0, 1><<<dim3(1, NE / BN, 4), NTHR, SMEM_BYTES>>>(
        yT, NN, mt, NN, eyT, NE, nullptr, NN / 4);

    scale_ey_kernel<<<(FOUT * NE / 4 + 255) / 256, 256>>>(eyT, dv);

    // G3: out[v][f] += 0.5*De[v] * sum_e MT[e][v] * eyT[f][e]   (split-K = 2)
    mmak<1, 2><<<dim3(NN / BM, 1, 2), NTHR, SMEM_BYTES>>>(
        mt, NN, eyT, NE, out, FOUT, de, NE / 2);
}

// round 14
// speedup vs baseline: 1.9635x; 1.6609x over previous
#include <cuda_runtime.h>
#include <cuda_fp16.h>
#include <cstdint>
#include <cstddef>

// ---------------------------------------------------------------------------
// HGNN_conv via fp16 mma.sync (m16n8k16, fp32 accumulate):
//   yT   = (x @ W)^T    fp16 [128f, 16384n]
//   eyT  = raw MT @ y   fp32 [128f, 8192e]  (split-K atomics)
//   eysh = fp16(D_v ⊙ ey)
//   out  = 0.5 * D_e ⊙ (MT^T @ eys)
// R14 = R13 with the __floats2half2_rn signature fixed (takes two floats).
// R12 skeleton (3-stage ring, proven schedule) with tf32 -> fp16: fp16
// mantissa (10 explicit bits) == tf32 precision, HMMA count halves (k16),
// operand smem bytes halve. G3's streamed MT uses ldmatrix.trans.
// ---------------------------------------------------------------------------

#define NN   16384
#define NE   8192
#define CIN  256
#define FOUT 128

__device__ __half g_yTh [FOUT * NN];   // 4 MB  fp16 (x@W)^T
__device__ float  g_eyT [FOUT * NE];   // 4 MB  fp32 raw (atomic target)
__device__ __half g_eysh[FOUT * NE];   // 2 MB  fp16 scaled
__device__ __half g_wth [FOUT * CIN];  // 64 KB fp16 W^T

#define BM 128
#define BN 128
#define BK 32
#define NTHR 256
#define SAH  40     // CONF0 A stride (halfs) = 80B
#define SBH  40     // B stride (halfs) = 80B
#define SA1H 136    // CONF1 A [k][m] stride (halfs) = 272B
#define STAGE_B 24576
#define B0_OFF_B 10240   // CONF0: B tile after 128*80B A tile
#define B1_OFF_B 8704    // CONF1: B tile after 32*272B A tile
#define NSTAGE 3
#define SMEM_BYTES 73728 // 3 stages * 24576; 2 CTAs/SM

// ---------------- helpers ----------------
static __device__ __forceinline__ uint32_t smem_u32(const void* p) {
    uint32_t a;
    asm("{ .reg .u64 t; cvta.to.shared.u64 t, %1; cvt.u32.u64 %0, t; }" : "=r"(a) : "l"(p));
    return a;
}
static __device__ __forceinline__ uint32_t h2(float a, float b) {
    __half2 h = __floats2half2_rn(a, b);
    return *reinterpret_cast<uint32_t*>(&h);
}
static __device__ __forceinline__ void cp16(uint32_t s, const void* g) {
    asm volatile("cp.async.cg.shared.global [%0], [%1], 16;" :: "r"(s), "l"(g) : "memory");
}
static __device__ __forceinline__ void cp_commit() {
    asm volatile("cp.async.commit_group;" ::: "memory");
}
static __device__ __forceinline__ void cp_wait0() {
    asm volatile("cp.async.wait_group 0;" ::: "memory");
}
static __device__ __forceinline__ void sts4(uint32_t a, uint32_t x, uint32_t y,
                                            uint32_t z, uint32_t w) {
    asm volatile("st.shared.v4.b32 [%0], {%1, %2, %3, %4};"
                 :: "r"(a), "r"(x), "r"(y), "r"(z), "r"(w) : "memory");
}
static __device__ __forceinline__ void ldsm4(uint32_t& r0, uint32_t& r1,
                                             uint32_t& r2, uint32_t& r3, uint32_t a) {
    asm volatile("ldmatrix.sync.aligned.m8n8.x4.shared.b16 {%0,%1,%2,%3}, [%4];"
                 : "=r"(r0), "=r"(r1), "=r"(r2), "=r"(r3) : "r"(a));
}
static __device__ __forceinline__ void ldsm4t(uint32_t& r0, uint32_t& r1,
                                              uint32_t& r2, uint32_t& r3, uint32_t a) {
    asm volatile("ldmatrix.sync.aligned.m8n8.x4.trans.shared.b16 {%0,%1,%2,%3}, [%4];"
                 : "=r"(r0), "=r"(r1), "=r"(r2), "=r"(r3) : "r"(a));
}
static __device__ __forceinline__ void mma16(float& c0, float& c1, float& c2, float& c3,
                                             uint32_t a0, uint32_t a1, uint32_t a2, uint32_t a3,
                                             uint32_t b0, uint32_t b1) {
    asm volatile("mma.sync.aligned.m16n8k16.row.col.f32.f16.f16.f32 "
                 "{%0,%1,%2,%3}, {%4,%5,%6,%7}, {%8,%9}, {%0,%1,%2,%3};"
                 : "+f"(c0), "+f"(c1), "+f"(c2), "+f"(c3)
                 : "r"(a0), "r"(a1), "r"(a2), "r"(a3), "r"(b0), "r"(b1));
}

// ---------------- small kernels ----------------
__global__ void zero2_kernel(float* __restrict__ a, size_t na4,
                             float* __restrict__ b, size_t nb4) {
    size_t i = (size_t)blockIdx.x * blockDim.x + threadIdx.x;
    size_t st = (size_t)gridDim.x * blockDim.x;
    float4 z = make_float4(0.f, 0.f, 0.f, 0.f);
    for (size_t j = i; j < na4; j += st) reinterpret_cast<float4*>(a)[j] = z;
    for (size_t j = i; j < nb4; j += st) reinterpret_cast<float4*>(b)[j] = z;
}
__global__ void prep_wt_kernel(const float* __restrict__ W, __half* __restrict__ wth) {
    int idx = blockIdx.x * blockDim.x + threadIdx.x;
    if (idx < FOUT * CIN) {
        int f = idx % FOUT, c = idx / FOUT;
        wth[f * CIN + c] = __float2half_rn(W[c * FOUT + f]);
    }
}
__global__ void scale_ey_kernel(const float* __restrict__ eyT,
                                const float* __restrict__ dv,
                                __half* __restrict__ eysh) {
    int i4 = blockIdx.x * blockDim.x + threadIdx.x;
    if (i4 < (FOUT * NE) / 4) {
        int e4 = (i4 * 4) & (NE - 1);
        float4 v = reinterpret_cast<const float4*>(eyT)[i4];
        const float4 s = *reinterpret_cast<const float4*>(&dv[e4]);
        uint2 o;
        o.x = h2(v.x * s.x, v.y * s.y);
        o.y = h2(v.z * s.z, v.w * s.w);
        reinterpret_cast<uint2*>(eysh)[i4] = o;
    }
}

// ---------------- main GEMM ----------------
// 256 threads, 8 warps (2x4), warp tile 64x32, K-tile 32 (2 x k16 groups).
// CONF 0: A resident fp16 [m][k] (cp.async);  B streamed fp32 -> fp16 STS [n][k]
// CONF 1: A streamed fp32 -> fp16 STS [k][m] (ldmatrix.trans); B resident fp16 [n][k]
// EPI  0: store __half2 (yT)   1: atomicAdd fp32   2: atomicAdd * 0.5*rowscale[m]
template <int CONF, int EPI>
__global__ __launch_bounds__(NTHR)
void mmak(const void* __restrict__ Agv, int lda,
          const void* __restrict__ Bgv, int ldb,
          void* __restrict__ Cgv, int ldc,
          const float* __restrict__ rowscale,
          int k_chunk)
{
    extern __shared__ char smc[];
    const int t    = threadIdx.x;
    const int lane = t & 31, wid = t >> 5;
    const int g = lane >> 2, tg = lane & 3;
    const int wm = (wid & 1) * 64, wn = (wid >> 1) * 32;
    const int m0 = blockIdx.x * BM, n0 = blockIdx.y * BN;
    const int kbase = blockIdx.z * k_chunk;
    const int KT = k_chunk / BK;

    float acc[4][4][4];
    #pragma unroll
    for (int a = 0; a < 4; ++a)
        #pragma unroll
        for (int b = 0; b < 4; ++b)
            #pragma unroll
            for (int c = 0; c < 4; ++c) acc[a][b][c] = 0.f;

    float4 rg[4];

    // per-lane fragment base offsets (bytes within a stage)
    uint32_t aOffB, bOffB;
    if (CONF == 0) {
        aOffB = (uint32_t)((wm + (lane & 15)) * (SAH * 2) + (lane >> 4) * 16);
        bOffB = (uint32_t)(B0_OFF_B
                + (wn + (lane & 7) + ((lane >> 4) & 1) * 8) * (SBH * 2)
                + ((lane >> 3) & 1) * 16);
    } else {
        aOffB = (uint32_t)(((lane & 7) + ((lane >> 4) & 1) * 8) * (SA1H * 2)
                + ((lane >> 3) & 1) * 16 + wm * 2);
        bOffB = (uint32_t)(B1_OFF_B
                + (wn + (lane & 7) + ((lane >> 4) & 1) * 8) * (SBH * 2)
                + ((lane >> 3) & 1) * 16);
    }

    // ---- streamed fp32 LDG into regs for tile kt ----
    auto ldg_stream = [&](int kt) {
        const int kk = kbase + kt * BK;
        if (CONF == 0) {
            const float* Bg = (const float*)Bgv;
            const int n = t >> 1, h = t & 1;
            const float4* src = reinterpret_cast<const float4*>(
                Bg + (size_t)(n0 + n) * ldb + kk + h * 16);
            #pragma unroll
            for (int j = 0; j < 4; ++j) rg[j] = src[j];
        } else {
            const float* Ag = (const float*)Agv;
            const int kr = t >> 3, ml = (t & 7) * 16;
            const float4* src = reinterpret_cast<const float4*>(
                Ag + (size_t)(kk + kr) * lda + m0 + ml);
            #pragma unroll
            for (int j = 0; j < 4; ++j) rg[j] = src[j];
        }
    };
    // ---- convert + STS streamed tile (fp16) into stage s ----
    auto sts_stream = [&](int s) {
        uint32_t u[8];
        #pragma unroll
        for (int j = 0; j < 4; ++j) {
            u[2 * j]     = h2(rg[j].x, rg[j].y);
            u[2 * j + 1] = h2(rg[j].z, rg[j].w);
        }
        uint32_t base = smem_u32(smc) + (uint32_t)s * STAGE_B;
        uint32_t a;
        if (CONF == 0) {
            const int n = t >> 1, h = t & 1;
            a = base + B0_OFF_B + (uint32_t)(n * (SBH * 2) + h * 32);
        } else {
            const int kr = t >> 3, ml = (t & 7) * 16;
            a = base + (uint32_t)(kr * (SA1H * 2) + ml * 2);
        }
        sts4(a,      u[0], u[1], u[2], u[3]);
        sts4(a + 16, u[4], u[5], u[6], u[7]);
    };
    // ---- resident fp16 operand via cp.async into stage s ----
    auto cp_res = [&](int s, int kt) {
        const int kk = kbase + kt * BK;
        uint32_t base = smem_u32(smc) + (uint32_t)s * STAGE_B;
        const int r = t >> 1, h = t & 1;
        if (CONF == 0) {
            const __half* Ah = (const __half*)Agv;
            const __half* src = Ah + (size_t)(m0 + r) * lda + kk + h * 16;
            uint32_t a = base + (uint32_t)(r * (SAH * 2) + h * 32);
            cp16(a, src);
            cp16(a + 16, src + 8);
        } else {
            const __half* Bh = (const __half*)Bgv;
            const __half* src = Bh + (size_t)(n0 + r) * ldb + kk + h * 16;
            uint32_t a = base + B1_OFF_B + (uint32_t)(r * (SBH * 2) + h * 32);
            cp16(a, src);
            cp16(a + 16, src + 8);
        }
    };
    // ---- compute one stage ----
    auto compute = [&](int s) {
        const uint32_t base = smem_u32(smc) + (uint32_t)s * STAGE_B;
        const uint32_t aBase = base + aOffB;
        const uint32_t bBase = base + bOffB;
        #pragma unroll
        for (int kg = 0; kg < 2; ++kg) {
            uint32_t af[4][4], bf[4][2];
            if (CONF == 0) {
                #pragma unroll
                for (int mi = 0; mi < 4; ++mi)
                    ldsm4(af[mi][0], af[mi][1], af[mi][2], af[mi][3],
                          aBase + kg * 32 + mi * (16 * SAH * 2));
            } else {
                #pragma unroll
                for (int mi = 0; mi < 4; ++mi)
                    ldsm4t(af[mi][0], af[mi][1], af[mi][2], af[mi][3],
                           aBase + kg * (16 * SA1H * 2) + mi * 32);
            }
            #pragma unroll
            for (int p = 0; p < 2; ++p)
                ldsm4(bf[2 * p][0], bf[2 * p][1], bf[2 * p + 1][0], bf[2 * p + 1][1],
                      bBase + kg * 32 + p * (16 * SBH * 2));
            #pragma unroll
            for (int mi = 0; mi < 4; ++mi)
                #pragma unroll
                for (int ni = 0; ni < 4; ++ni)
                    mma16(acc[mi][ni][0], acc[mi][ni][1], acc[mi][ni][2], acc[mi][ni][3],
                          af[mi][0], af[mi][1], af[mi][2], af[mi][3],
                          bf[ni][0], bf[ni][1]);
        }
    };

    // ---- prologue: fill stage 0 (R12 schedule) ----
    ldg_stream(0);
    sts_stream(0);
    cp_res(0, 0);
    cp_commit();

    // ---- main loop: 3-stage ring, single barrier per stage (R12) ----
    for (int kt = 0; kt < KT; ++kt) {
        const int cur = kt % NSTAGE, nxt = (kt + 1) % NSTAGE;
        const bool more = (kt + 1 < KT);
        if (more) ldg_stream(kt + 1);
        cp_wait0();
        __syncthreads();
        if (more) {
            sts_stream(nxt);
            cp_res(nxt, kt + 1);
            cp_commit();
        }
        compute(cur);
    }

    // ---- epilogue ----
    #pragma unroll
    for (int mi = 0; mi < 4; ++mi) {
        const int r0 = m0 + wm + mi * 16 + g;
        const int r1 = r0 + 8;
        #pragma unroll
        for (int ni = 0; ni < 4; ++ni) {
            const int c0 = n0 + wn + ni * 8 + tg * 2;
            if (EPI == 0) {
                __half* Ch = (__half*)Cgv;
                *reinterpret_cast<__half2*>(Ch + (size_t)r0 * ldc + c0) =
                    __floats2half2_rn(acc[mi][ni][0], acc[mi][ni][1]);
                *reinterpret_cast<__half2*>(Ch + (size_t)r1 * ldc + c0) =
                    __floats2half2_rn(acc[mi][ni][2], acc[mi][ni][3]);
            } else if (EPI == 1) {
                float* Cg = (float*)Cgv;
                float* p0 = Cg + (size_t)r0 * ldc + c0;
                float* p1 = Cg + (size_t)r1 * ldc + c0;
                atomicAdd(&p0[0], acc[mi][ni][0]); atomicAdd(&p0[1], acc[mi][ni][1]);
                atomicAdd(&p1[0], acc[mi][ni][2]); atomicAdd(&p1[1], acc[mi][ni][3]);
            } else {
                float* Cg = (float*)Cgv;
                float* p0 = Cg + (size_t)r0 * ldc + c0;
                float* p1 = Cg + (size_t)r1 * ldc + c0;
                const float s0 = 0.5f * rowscale[r0];
                const float s1 = 0.5f * rowscale[r1];
                atomicAdd(&p0[0], s0 * acc[mi][ni][0]); atomicAdd(&p0[1], s0 * acc[mi][ni][1]);
                atomicAdd(&p1[0], s1 * acc[mi][ni][2]); atomicAdd(&p1[1], s1 * acc[mi][ni][3]);
            }
        }
    }
}

// ---------------- launch ----------------
extern "C" void kernel_launch(void* const* d_in, const int* in_sizes, int n_in,
                              void* d_out, int out_size) {
    const float *x = nullptr, *w = nullptr, *mt = nullptr, *dv = nullptr, *de = nullptr;
    for (int i = 0; i < n_in; ++i) {
        switch (in_sizes[i]) {
            case NN * CIN:   x  = (const float*)d_in[i]; break;
            case CIN * FOUT: w  = (const float*)d_in[i]; break;
            case 134217728:  mt = (const float*)d_in[i]; break;
            case NE:         dv = (const float*)d_in[i]; break;
            case NN:         de = (const float*)d_in[i]; break;
        }
    }
    float* out = (float*)d_out;
    __half *yTh, *eysh, *wth;
    float *eyT;
    { void* p; cudaGetSymbolAddress(&p, g_yTh);  yTh  = (__half*)p; }
    { void* p; cudaGetSymbolAddress(&p, g_eyT);  eyT  = (float*)p; }
    { void* p; cudaGetSymbolAddress(&p, g_eysh); eysh = (__half*)p; }
    { void* p; cudaGetSymbolAddress(&p, g_wth);  wth  = (__half*)p; }

    cudaFuncSetAttribute(mmak<0, 0>, cudaFuncAttributeMaxDynamicSharedMemorySize, SMEM_BYTES);
    cudaFuncSetAttribute(mmak<0, 1>, cudaFuncAttributeMaxDynamicSharedMemorySize, SMEM_BYTES);
    cudaFuncSetAttribute(mmak<1, 2>, cudaFuncAttributeMaxDynamicSharedMemorySize, SMEM_BYTES);

    zero2_kernel<<<512, 256>>>(eyT, (size_t)(FOUT * NE) / 4, out, (size_t)(NN * FOUT) / 4);
    prep_wt_kernel<<<(FOUT * CIN + 255) / 256, 256>>>(w, wth);

    // G1: yTh[f][n] = fp16( sum_c wth[f][c] * x[n][c] )
    mmak<0, 0><<<dim3(1, NN / BN, 1), NTHR, SMEM_BYTES>>>(
        wth, CIN, x, CIN, yTh, NN, nullptr, CIN);

    // G2: eyT[f][e] += sum_n yTh[f][n] * fp16(MT[e][n])   (split-K = 4)
    mmak<0, 1><<<dim3(1, NE / BN, 4), NTHR, SMEM_BYTES>>>(
        yTh, NN, mt, NN, eyT, NE, nullptr, NN / 4);

    scale_ey_kernel<<<(FOUT * NE / 4 + 255) / 256, 256>>>(eyT, dv, eysh);

    // G3: out[v][f] += 0.5*De[v] * sum_e fp16(MT[e][v]) * eysh[f][e]  (split-K = 2)
    mmak<1, 2><<<dim3(NN / BM, 1, 2), NTHR, SMEM_BYTES>>>(
        mt, NN, eysh, NE, out, FOUT, de, NE / 2);
}